// round 9
// baseline (speedup 1.0000x reference)
#include <cuda_runtime.h>
#include <math.h>

#define TL 513
#define NN (TL*8)   // 4104

__device__ float g_c1[8*512*1025];
__device__ float g_xin[TL*8*576];
__device__ float g_G0[TL*8*2048];
__device__ float g_h0[TL*8*512];
__device__ float g_h1[TL*8*512];
__device__ float g_q [TL*8*512];
__device__ float g_k [TL*8*512];
__device__ float g_cn[TL*8*512];
__device__ float g_at[TL*8*512];
__device__ float g_fc[TL*8*512];
__device__ float g_y [TL*8*512];
__device__ float g_ps[33*512];
__device__ float g_pq[33*512];
__device__ float g_st[1024];
__device__ unsigned g_bar;

__global__ void bar_reset() { g_bar = 0u; }

// ---- packed f32x2 helpers (sm_103a) ---------------------------------------
__device__ __forceinline__ unsigned long long ffma2(
    unsigned long long a, unsigned long long b, unsigned long long c)
{
    unsigned long long d;
    asm("fma.rn.f32x2 %0, %1, %2, %3;" : "=l"(d) : "l"(a), "l"(b), "l"(c));
    return d;
}
__device__ __forceinline__ unsigned long long dup2(float x)
{
    unsigned long long r;
    asm("mov.b64 %0, {%1, %1};" : "=l"(r) : "f"(x));
    return r;
}
__device__ __forceinline__ float2 upk2(unsigned long long v)
{
    float2 f;
    asm("mov.b64 {%0, %1}, %2;" : "=f"(f.x), "=f"(f.y) : "l"(v));
    return f;
}

// release-add arrive / acquire-load peek on the global step counter
__device__ __forceinline__ void bar_arrive(unsigned* p)
{
    asm volatile("red.release.gpu.global.add.u32 [%0], %1;" :: "l"(p), "r"(1u) : "memory");
}
__device__ __forceinline__ unsigned bar_peek(const unsigned* p)
{
    unsigned v;
    asm volatile("ld.acquire.gpu.global.u32 %0, [%1];" : "=r"(v) : "l"(p) : "memory");
    return v;
}

// ---------------------------------------------------------------------------
// Conv1d K=4, stride 2, pad 2, + ReLU.  FFMA2 inner loop.
// ---------------------------------------------------------------------------
__global__ __launch_bounds__(128) void conv_relu(
    const float* __restrict__ in, const float* __restrict__ w,
    const float* __restrict__ bias, float* __restrict__ out,
    int Cin, int Lin, int Lout, int mode)
{
    __shared__ float sIn[8][260];
    __shared__ float sW[16][8][4];
    int tid = threadIdx.x;
    int b = blockIdx.z, coBase = blockIdx.y * 16, tBase = blockIdx.x * 128;
    int base = 2 * tBase - 2;
    int tg = tid & 15, co_l = tid >> 4;
    unsigned long long acc0p[8], acc1p[8];
#pragma unroll
    for (int i = 0; i < 8; i++) { acc0p[i] = 0ull; acc1p[i] = 0ull; }

    for (int c0 = 0; c0 < Cin; c0 += 8) {
        for (int x = tid; x < 8 * 258; x += 128) {
            int ci = x / 258, li = x - ci * 258, p = base + li, cig = c0 + ci;
            float v = 0.f;
            if (cig < Cin && p >= 0 && p < Lin)
                v = in[(size_t)b * Cin * Lin + (size_t)cig * Lin + p];
            sIn[ci][li] = v;
        }
        for (int x = tid; x < 512; x += 128) {
            int co = x >> 5, ci = (x >> 2) & 7, kk = x & 3, cig = c0 + ci;
            sW[co][ci][kk] = (cig < Cin) ? w[((size_t)(coBase + co) * Cin + cig) * 4 + kk] : 0.f;
        }
        __syncthreads();
#pragma unroll
        for (int ci = 0; ci < 8; ci++) {
            ulonglong2 wq0 = *(const ulonglong2*)&sW[co_l][ci][0];
            ulonglong2 wq1 = *(const ulonglong2*)&sW[co_l + 8][ci][0];
#pragma unroll
            for (int jj = 0; jj < 8; jj++) {
                int li = 2 * tg + 32 * jj;
                unsigned long long pa = *(const unsigned long long*)&sIn[ci][li];
                unsigned long long pb = *(const unsigned long long*)&sIn[ci][li + 2];
                acc0p[jj] = ffma2(wq0.x, pa, acc0p[jj]);
                acc0p[jj] = ffma2(wq0.y, pb, acc0p[jj]);
                acc1p[jj] = ffma2(wq1.x, pa, acc1p[jj]);
                acc1p[jj] = ffma2(wq1.y, pb, acc1p[jj]);
            }
        }
        __syncthreads();
    }
    int co0 = coBase + co_l, co1 = co0 + 8;
    float b0 = bias[co0], b1 = bias[co1];
#pragma unroll
    for (int jj = 0; jj < 8; jj++) {
        int t = tBase + tg + 16 * jj;
        if (t < Lout) {
            float2 f0 = upk2(acc0p[jj]);
            float2 f1 = upk2(acc1p[jj]);
            float v0 = fmaxf(f0.x + f0.y + b0, 0.f);
            float v1 = fmaxf(f1.x + f1.y + b1, 0.f);
            if (mode == 0) {
                out[(size_t)b * 512 * Lout + (size_t)co0 * Lout + t] = v0;
                out[(size_t)b * 512 * Lout + (size_t)co1 * Lout + t] = v1;
            } else {
                out[(size_t)t * 4608 + b * 576 + co0] = v0;
                out[(size_t)t * 4608 + b * 576 + co1] = v1;
            }
        }
    }
}

__global__ void embfill(const float* __restrict__ emb, const int* __restrict__ subj,
                        float* __restrict__ xin)
{
    int idx = blockIdx.x * blockDim.x + threadIdx.x;
    if (idx >= TL * 8 * 64) return;
    int e = idx & 63, b = (idx >> 6) & 7, t = idx >> 9;
    xin[(size_t)t * 4608 + b * 576 + 512 + e] = emb[(size_t)subj[b] * 64 + e];
}

// ---------------------------------------------------------------------------
// GEMM 128x128 tile, 8x8 micro, FFMA2 packed over output columns (j pairs).
// mode 0: C[n*M+m]; mode 1: d_out[(b*128+m)*513+t], n=t*8+b (M=128 only).
// ---------------------------------------------------------------------------
__global__ __launch_bounds__(256) void gemm_nt(
    const float* __restrict__ Wm, const float* __restrict__ Bm, float* __restrict__ C,
    const float* __restrict__ bias1, const float* __restrict__ bias2,
    int M, int N, int K, int mode)
{
    __shared__ float sA[16 * 132];
    __shared__ float sB[16 * 132];
    int tid = threadIdx.x;
    int mBase = blockIdx.y * 128, nBase = blockIdx.x * 128;
    int r = tid & 127, kq = (tid >> 7) * 8;
    int mi = (tid & 15) * 4, ni = ((tid >> 4) & 15) * 4;

    unsigned long long accp[8][4];
#pragma unroll
    for (int i = 0; i < 8; i++)
#pragma unroll
        for (int jp = 0; jp < 4; jp++) accp[i][jp] = 0ull;

    float4 a0, a1, b0v, b1v;
    {
        const float* ap = &Wm[(size_t)(mBase + r) * K + kq];
        a0 = *(const float4*)ap; a1 = *(const float4*)(ap + 4);
        int n = nBase + r;
        if (n < N) {
            const float* bp = &Bm[(size_t)n * K + kq];
            b0v = *(const float4*)bp; b1v = *(const float4*)(bp + 4);
        } else { b0v = make_float4(0,0,0,0); b1v = b0v; }
    }

    for (int k0 = 0; k0 < K; k0 += 16) {
        __syncthreads();
        sA[(kq+0)*132+r]=a0.x; sA[(kq+1)*132+r]=a0.y; sA[(kq+2)*132+r]=a0.z; sA[(kq+3)*132+r]=a0.w;
        sA[(kq+4)*132+r]=a1.x; sA[(kq+5)*132+r]=a1.y; sA[(kq+6)*132+r]=a1.z; sA[(kq+7)*132+r]=a1.w;
        sB[(kq+0)*132+r]=b0v.x; sB[(kq+1)*132+r]=b0v.y; sB[(kq+2)*132+r]=b0v.z; sB[(kq+3)*132+r]=b0v.w;
        sB[(kq+4)*132+r]=b1v.x; sB[(kq+5)*132+r]=b1v.y; sB[(kq+6)*132+r]=b1v.z; sB[(kq+7)*132+r]=b1v.w;
        __syncthreads();
        int kn = k0 + 16;
        if (kn < K) {
            const float* ap = &Wm[(size_t)(mBase + r) * K + kn + kq];
            a0 = *(const float4*)ap; a1 = *(const float4*)(ap + 4);
            int n = nBase + r;
            if (n < N) {
                const float* bp = &Bm[(size_t)n * K + kn + kq];
                b0v = *(const float4*)bp; b1v = *(const float4*)(bp + 4);
            } else { b0v = make_float4(0,0,0,0); b1v = b0v; }
        }
#pragma unroll
        for (int kk = 0; kk < 16; kk++) {
            float4 aL = *(const float4*)&sA[kk * 132 + mi];
            float4 aH = *(const float4*)&sA[kk * 132 + mi + 64];
            ulonglong2 bLp = *(const ulonglong2*)&sB[kk * 132 + ni];
            ulonglong2 bHp = *(const ulonglong2*)&sB[kk * 132 + ni + 64];
            unsigned long long ad[8];
            ad[0]=dup2(aL.x); ad[1]=dup2(aL.y); ad[2]=dup2(aL.z); ad[3]=dup2(aL.w);
            ad[4]=dup2(aH.x); ad[5]=dup2(aH.y); ad[6]=dup2(aH.z); ad[7]=dup2(aH.w);
            unsigned long long bp[4] = {bLp.x, bLp.y, bHp.x, bHp.y};
#pragma unroll
            for (int i = 0; i < 8; i++)
#pragma unroll
                for (int jp = 0; jp < 4; jp++)
                    accp[i][jp] = ffma2(ad[i], bp[jp], accp[i][jp]);
        }
    }

    float acc[8][8];
#pragma unroll
    for (int i = 0; i < 8; i++)
#pragma unroll
        for (int jp = 0; jp < 4; jp++) {
            float2 f = upk2(accp[i][jp]);
            acc[i][2*jp] = f.x; acc[i][2*jp+1] = f.y;
        }

    float bb[8];
#pragma unroll
    for (int i = 0; i < 8; i++) {
        int m = mBase + ((i < 4) ? (mi + i) : (64 + mi + i - 4));
        float v = bias1 ? bias1[m] : 0.f;
        if (bias2) v += bias2[m];
        bb[i] = v;
    }
    if (mode == 0) {
#pragma unroll
        for (int j = 0; j < 8; j++) {
            int n = nBase + ((j < 4) ? (ni + j) : (64 + ni + j - 4));
            if (n < N) {
                float4 lo = make_float4(acc[0][j]+bb[0], acc[1][j]+bb[1], acc[2][j]+bb[2], acc[3][j]+bb[3]);
                float4 hi = make_float4(acc[4][j]+bb[4], acc[5][j]+bb[5], acc[6][j]+bb[6], acc[7][j]+bb[7]);
                *(float4*)&C[(size_t)n * M + mBase + mi] = lo;
                *(float4*)&C[(size_t)n * M + mBase + mi + 64] = hi;
            }
        }
    } else {
#pragma unroll
        for (int j = 0; j < 8; j++) {
            int n = nBase + ((j < 4) ? (ni + j) : (64 + ni + j - 4));
            if (n < N) {
                int bI = n & 7, t = n >> 3;
#pragma unroll
                for (int i = 0; i < 8; i++) {
                    int m = mBase + ((i < 4) ? (mi + i) : (64 + mi + i - 4));
                    C[(size_t)(bI * 128 + m) * 513 + t] = acc[i][j] + bb[i];
                }
            }
        }
    }
}

// ---------------------------------------------------------------------------
// Fused 2-layer wavefront LSTM.  128 CTAs x 256 thr (8 warps).
// Warps 0-3: layer0 unit u=blk*4+w; warps 4-7: layer1 unit u=blk*4+w-4.
// Step s: layer0 does t=s, layer1 does t=s-1.  Release/acquire counter
// barrier: syncthreads -> tid0 red.release add -> all threads acquire-spin.
// ---------------------------------------------------------------------------
__global__ __launch_bounds__(256) void lstm2_kernel(
    const float* __restrict__ Whh0, const float* __restrict__ Gpre0,
    const float* __restrict__ Wih1, const float* __restrict__ Whh1,
    const float* __restrict__ bih1, const float* __restrict__ bhh1,
    float* __restrict__ h0seq, float* __restrict__ h1seq)
{
    __shared__ float bufA[4096];
    __shared__ float bufB[4096];
    unsigned* barp = &g_bar;
    int tid = threadIdx.x;
    int w = tid >> 5, l = tid & 31;
    int layer = w >> 2;
    int u = blockIdx.x * 4 + (w & 3);
    int gg = l >> 3, bb = l & 7;

    const float* Wrec = (layer == 0) ? Whh0 : Whh1;
    ulonglong2 wrp[4][4];
#pragma unroll
    for (int g = 0; g < 4; g++)
#pragma unroll
        for (int cc = 0; cc < 4; cc++)
            wrp[g][cc] = *(const ulonglong2*)&Wrec[(size_t)(g * 512 + u) * 512 + cc * 128 + (l << 2)];
    ulonglong2 wip[4][4];
    if (layer == 1) {
#pragma unroll
        for (int g = 0; g < 4; g++)
#pragma unroll
            for (int cc = 0; cc < 4; cc++)
                wip[g][cc] = *(const ulonglong2*)&Wih1[(size_t)(g * 512 + u) * 512 + cc * 128 + (l << 2)];
    } else {
#pragma unroll
        for (int g = 0; g < 4; g++)
#pragma unroll
            for (int cc = 0; cc < 4; cc++)
                wip[g][cc] = make_ulonglong2(0ull, 0ull);
    }
    float bias1v = (layer == 1) ? (bih1[gg * 512 + u] + bhh1[gg * 512 + u]) : 0.f;

    float c = 0.f;

    for (int s = 0; s <= TL; s++) {
        // fill bufA = h0[s-1], bufB = h1[s-2]
        if (s == 0) {
            for (int i = tid; i < 1024; i += 256) ((float4*)bufA)[i] = make_float4(0,0,0,0);
        } else {
            const float4* src = (const float4*)(h0seq + (size_t)(s - 1) * 4096);
            for (int i = tid; i < 1024; i += 256) ((float4*)bufA)[i] = __ldcg(&src[i]);
        }
        if (s <= 1) {
            for (int i = tid; i < 1024; i += 256) ((float4*)bufB)[i] = make_float4(0,0,0,0);
        } else {
            const float4* src = (const float4*)(h1seq + (size_t)(s - 2) * 4096);
            for (int i = tid; i < 1024; i += 256) ((float4*)bufB)[i] = __ldcg(&src[i]);
        }
        __syncthreads();

        int t = (layer == 0) ? s : (s - 1);
        bool active = (t >= 0) && (t < TL);
        if (active) {
            float gpre;
            if (layer == 0)
                gpre = Gpre0[(size_t)(t * 8 + bb) * 2048 + gg * 512 + u];
            else
                gpre = bias1v;

            unsigned long long accp[4][8];
#pragma unroll
            for (int g = 0; g < 4; g++)
#pragma unroll
                for (int q = 0; q < 8; q++) accp[g][q] = 0ull;

            const float* hrec = (layer == 0) ? bufA : bufB;
#pragma unroll
            for (int q = 0; q < 8; q++) {
                const float* hb = hrec + q * 512 + (l << 2);
#pragma unroll
                for (int cc = 0; cc < 4; cc++) {
                    ulonglong2 hp = *(const ulonglong2*)(hb + cc * 128);
#pragma unroll
                    for (int g = 0; g < 4; g++) {
                        accp[g][q] = ffma2(wrp[g][cc].x, hp.x, accp[g][q]);
                        accp[g][q] = ffma2(wrp[g][cc].y, hp.y, accp[g][q]);
                    }
                }
            }
            if (layer == 1) {
#pragma unroll
                for (int q = 0; q < 8; q++) {
                    const float* hb = bufA + q * 512 + (l << 2);
#pragma unroll
                    for (int cc = 0; cc < 4; cc++) {
                        ulonglong2 hp = *(const ulonglong2*)(hb + cc * 128);
#pragma unroll
                        for (int g = 0; g < 4; g++) {
                            accp[g][q] = ffma2(wip[g][cc].x, hp.x, accp[g][q]);
                            accp[g][q] = ffma2(wip[g][cc].y, hp.y, accp[g][q]);
                        }
                    }
                }
            }

            float v[32];
#pragma unroll
            for (int g = 0; g < 4; g++)
#pragma unroll
                for (int q = 0; q < 8; q++) {
                    float2 f = upk2(accp[g][q]);
                    v[g * 8 + q] = f.x + f.y;
                }
            int cnt = 32;
#pragma unroll
            for (int sft = 16; sft >= 1; sft >>= 1) {
                cnt >>= 1;
                bool up = (l & sft) != 0;
#pragma unroll
                for (int i = 0; i < cnt; i++) {
                    float give = up ? v[i] : v[i + cnt];
                    float keep = up ? v[i + cnt] : v[i];
                    v[i] = keep + __shfl_xor_sync(0xffffffffu, give, sft);
                }
            }
            float val = v[0] + gpre;
            float iv = __shfl_sync(0xffffffffu, val, bb);
            float fv = __shfl_sync(0xffffffffu, val, 8 + bb);
            float gv = __shfl_sync(0xffffffffu, val, 16 + bb);
            float ov = __shfl_sync(0xffffffffu, val, 24 + bb);
            if (l < 8) {
                float si = 1.f / (1.f + __expf(-iv));
                float sf = 1.f / (1.f + __expf(-fv));
                float so = 1.f / (1.f + __expf(-ov));
                c = sf * c + si * tanhf(gv);
                float h = so * tanhf(c);
                float* dst = (layer == 0) ? h0seq : h1seq;
                dst[(size_t)(t * 8 + l) * 512 + u] = h;
            }
        }
        // barrier: publish this CTA's stores, arrive, spin (all threads)
        __syncthreads();
        if (tid == 0) bar_arrive(barp);
        if (s < TL) {
            unsigned target = 128u * (unsigned)(s + 1);
            while (bar_peek(barp) < target) {}
        }
    }
}

// ---------------------------------------------------------------------------
// Banded rel-pos attention.
// ---------------------------------------------------------------------------
__global__ __launch_bounds__(128) void attn_kernel(
    const float* __restrict__ q, const float* __restrict__ k,
    const float* __restrict__ cn, const float* __restrict__ rel,
    float* __restrict__ outp)
{
    extern __shared__ float sm[];
    float* sq = sm;
    float* sk = sq + 16 * 64;
    float* sc = sk + 116 * 64;
    float* se = sc + 116 * 64;
    float* sw = se + 101 * 64;
    int t0 = blockIdx.x * 16, hh = blockIdx.y, b = blockIdx.z;
    int tid = threadIdx.x;
    int s0 = t0 - 50;

    for (int i = tid; i < 16 * 64; i += 128) {
        int r = i >> 6, cc = i & 63; int t = t0 + r;
        sq[i] = (t < TL) ? q[(size_t)(t * 8 + b) * 512 + hh * 64 + cc] : 0.f;
    }
    for (int i = tid; i < 116 * 64; i += 128) {
        int r = i >> 6, cc = i & 63; int s = s0 + r;
        float kv = 0.f, cv = 0.f;
        if (s >= 0 && s < TL) {
            size_t base = (size_t)(s * 8 + b) * 512 + hh * 64 + cc;
            kv = k[base]; cv = cn[base];
        }
        sk[i] = kv; sc[i] = cv;
    }
    for (int i = tid; i < 101 * 64; i += 128) se[i] = rel[i];
    __syncthreads();

    int row = tid >> 3, l8 = tid & 7;
    int t = t0 + row;
    float sco[13];
    float mx = -1e30f;
#pragma unroll
    for (int j = 0; j < 13; j++) {
        int sl = l8 + 8 * j;
        int s = t - 50 + sl;
        float v = -1e30f;
        if (sl <= 100 && s >= 0 && s < TL && t < TL) {
            const float4* qp = (const float4*)(sq + row * 64);
            const float4* kp = (const float4*)(sk + (row + sl) * 64);
            const float4* ep = (const float4*)(se + (100 - sl) * 64);
            float a = 0.f;
#pragma unroll
            for (int c4 = 0; c4 < 16; c4++) {
                float4 qv = qp[c4], kv = kp[c4], ev = ep[c4];
                a += qv.x * (kv.x + 0.3f * ev.x) + qv.y * (kv.y + 0.3f * ev.y)
                   + qv.z * (kv.z + 0.3f * ev.z) + qv.w * (kv.w + 0.3f * ev.w);
            }
            v = a;
        }
        sco[j] = v;
        mx = fmaxf(mx, v);
    }
    mx = fmaxf(mx, __shfl_xor_sync(0xffffffffu, mx, 1));
    mx = fmaxf(mx, __shfl_xor_sync(0xffffffffu, mx, 2));
    mx = fmaxf(mx, __shfl_xor_sync(0xffffffffu, mx, 4));
    float sum = 0.f;
#pragma unroll
    for (int j = 0; j < 13; j++) {
        float e = (sco[j] > -1e29f) ? __expf(sco[j] - mx) : 0.f;
        sco[j] = e; sum += e;
    }
    sum += __shfl_xor_sync(0xffffffffu, sum, 1);
    sum += __shfl_xor_sync(0xffffffffu, sum, 2);
    sum += __shfl_xor_sync(0xffffffffu, sum, 4);
    float inv = 1.f / sum;
#pragma unroll
    for (int j = 0; j < 13; j++) sw[row * 104 + l8 + 8 * j] = sco[j] * inv;
    __syncwarp();

    float4 a0 = make_float4(0.f, 0.f, 0.f, 0.f), a1 = a0;
    for (int sl = 0; sl <= 100; sl++) {
        float wv = sw[row * 104 + sl];
        const float* cp = sc + (row + sl) * 64 + l8 * 8;
        const float* ep = se + (100 - sl) * 64 + l8 * 8;
        float4 c0v = *(const float4*)cp;
        float4 c1v = *(const float4*)(cp + 4);
        float4 e0 = *(const float4*)ep;
        float4 e1 = *(const float4*)(ep + 4);
        a0.x += wv * (c0v.x + 0.3f * e0.x); a0.y += wv * (c0v.y + 0.3f * e0.y);
        a0.z += wv * (c0v.z + 0.3f * e0.z); a0.w += wv * (c0v.w + 0.3f * e0.w);
        a1.x += wv * (c1v.x + 0.3f * e1.x); a1.y += wv * (c1v.y + 0.3f * e1.y);
        a1.z += wv * (c1v.z + 0.3f * e1.z); a1.w += wv * (c1v.w + 0.3f * e1.w);
    }
    if (t < TL) {
        float* op = outp + (size_t)(t * 8 + b) * 512 + hh * 64 + l8 * 8;
        *(float4*)op = a0;
        *(float4*)(op + 4) = a1;
    }
}

__global__ void bn_part(const float* __restrict__ x, float* __restrict__ ps,
                        float* __restrict__ pq)
{
    int p = blockIdx.x, ch = threadIdx.x;
    int n0 = p * 128, n1 = n0 + 128; if (n1 > NN) n1 = NN;
    float s = 0.f, qq = 0.f;
    for (int n = n0; n < n1; n++) {
        float v = x[(size_t)n * 512 + ch];
        s += v; qq += v * v;
    }
    ps[p * 512 + ch] = s; pq[p * 512 + ch] = qq;
}

__global__ void bn_fin(const float* __restrict__ ps, const float* __restrict__ pq,
                       float* __restrict__ st)
{
    int c = threadIdx.x;
    float s = 0.f, qq = 0.f;
    for (int p = 0; p < 33; p++) { s += ps[p * 512 + c]; qq += pq[p * 512 + c]; }
    float mu = s / (float)NN;
    float var = qq / (float)NN - mu * mu;
    st[c] = mu;
    st[512 + c] = rsqrtf(var + 1e-5f);
}

__global__ void fuse_kernel(const float* __restrict__ h1, const float* __restrict__ fc,
                            const float* __restrict__ st, const float* __restrict__ g,
                            const float* __restrict__ b, const float* __restrict__ sc,
                            float* __restrict__ y)
{
    int idx = blockIdx.x * blockDim.x + threadIdx.x;
    if (idx >= NN * 512) return;
    int c = idx & 511;
    float v = (fc[idx] - st[c]) * st[512 + c] * g[c] + b[c];
    v = fmaxf(v, 0.f) * sc[c];
    y[idx] = h1[idx] + v;
}

extern "C" void kernel_launch(void* const* d_in, const int* in_sizes, int n_in,
                              void* d_out, int out_size)
{
    const float* meg  = (const float*)d_in[0];
    const float* c1w  = (const float*)d_in[1];
    const float* c1b  = (const float*)d_in[2];
    const float* c2w  = (const float*)d_in[3];
    const float* c2b  = (const float*)d_in[4];
    const float* semb = (const float*)d_in[5];
    const float* Wih0 = (const float*)d_in[6];
    const float* Whh0 = (const float*)d_in[7];
    const float* bih0 = (const float*)d_in[8];
    const float* bhh0 = (const float*)d_in[9];
    const float* Wih1 = (const float*)d_in[10];
    const float* Whh1 = (const float*)d_in[11];
    const float* bih1 = (const float*)d_in[12];
    const float* bhh1 = (const float*)d_in[13];
    const float* qw = (const float*)d_in[14];
    const float* qb = (const float*)d_in[15];
    const float* kw = (const float*)d_in[16];
    const float* kb = (const float*)d_in[17];
    const float* cw = (const float*)d_in[18];
    const float* cb = (const float*)d_in[19];
    const float* rel = (const float*)d_in[20];
    const float* fcw = (const float*)d_in[21];
    const float* fcb = (const float*)d_in[22];
    const float* bng = (const float*)d_in[23];
    const float* bnb = (const float*)d_in[24];
    const float* ascale = (const float*)d_in[25];
    const float* ow = (const float*)d_in[26];
    const float* ob = (const float*)d_in[27];
    const int* subj = (const int*)d_in[28];
    float* out = (float*)d_out;

    float *c1p, *xinp, *G0p, *h0p, *h1p, *qp, *kp, *cnp, *atp, *fcp, *yp, *psp, *pqp, *stp;
    cudaGetSymbolAddress((void**)&c1p,  g_c1);
    cudaGetSymbolAddress((void**)&xinp, g_xin);
    cudaGetSymbolAddress((void**)&G0p,  g_G0);
    cudaGetSymbolAddress((void**)&h0p,  g_h0);
    cudaGetSymbolAddress((void**)&h1p,  g_h1);
    cudaGetSymbolAddress((void**)&qp,   g_q);
    cudaGetSymbolAddress((void**)&kp,   g_k);
    cudaGetSymbolAddress((void**)&cnp,  g_cn);
    cudaGetSymbolAddress((void**)&atp,  g_at);
    cudaGetSymbolAddress((void**)&fcp,  g_fc);
    cudaGetSymbolAddress((void**)&yp,   g_y);
    cudaGetSymbolAddress((void**)&psp,  g_ps);
    cudaGetSymbolAddress((void**)&pqp,  g_pq);
    cudaGetSymbolAddress((void**)&stp,  g_st);

    cudaFuncSetAttribute(attn_kernel, cudaFuncAttributeMaxDynamicSharedMemorySize, 96000);

    conv_relu<<<dim3(9, 32, 8), 128>>>(meg, c1w, c1b, c1p, 273, 2048, 1025, 0);
    conv_relu<<<dim3(5, 32, 8), 128>>>(c1p, c2w, c2b, xinp, 512, 1025, 513, 1);
    embfill<<<(TL * 8 * 64 + 255) / 256, 256>>>(semb, subj, xinp);

    gemm_nt<<<dim3(33, 16), 256>>>(Wih0, xinp, G0p, bih0, bhh0, 2048, NN, 576, 0);
    bar_reset<<<1, 1>>>();
    lstm2_kernel<<<128, 256>>>(Whh0, G0p, Wih1, Whh1, bih1, bhh1, h0p, h1p);

    gemm_nt<<<dim3(33, 4), 256>>>(qw, h1p, qp, qb, (const float*)0, 512, NN, 512, 0);
    gemm_nt<<<dim3(33, 4), 256>>>(kw, h1p, kp, kb, (const float*)0, 512, NN, 512, 0);
    gemm_nt<<<dim3(33, 4), 256>>>(cw, h1p, cnp, cb, (const float*)0, 512, NN, 512, 0);

    attn_kernel<<<dim3(33, 8, 8), 128, 96000>>>(qp, kp, cnp, rel, atp);

    gemm_nt<<<dim3(33, 4), 256>>>(fcw, atp, fcp, fcb, (const float*)0, 512, NN, 512, 0);
    bn_part<<<33, 512>>>(fcp, psp, pqp);
    bn_fin<<<1, 512>>>(psp, pqp, stp);
    fuse_kernel<<<(NN * 512 + 255) / 256, 256>>>(h1p, fcp, stp, bng, bnb, ascale, yp);

    gemm_nt<<<dim3(33, 1), 256>>>(ow, yp, out, ob, (const float*)0, 128, NN, 512, 1);
}

// round 10
// speedup vs baseline: 1.0650x; 1.0650x over previous
#include <cuda_runtime.h>
#include <math.h>

#define TL 513
#define NN (TL*8)   // 4104

__device__ float g_c1[8*512*1025];
__device__ float g_xin[TL*8*576];
__device__ float g_G0[TL*8*2048];
__device__ float g_h0[TL*8*512];
__device__ float g_h1[TL*8*512];
__device__ float g_q [TL*8*512];
__device__ float g_k [TL*8*512];
__device__ float g_cn[TL*8*512];
__device__ float g_at[TL*8*512];
__device__ float g_fc[TL*8*512];
__device__ float g_y [TL*8*512];
__device__ float g_ps[33*512];
__device__ float g_pq[33*512];
__device__ float g_st[1024];
__device__ unsigned g_bar;
__device__ unsigned g_flag;

__global__ void bar_reset() { g_bar = 0u; g_flag = 0u; }

// ---- packed f32x2 helpers (sm_103a) ---------------------------------------
__device__ __forceinline__ unsigned long long ffma2(
    unsigned long long a, unsigned long long b, unsigned long long c)
{
    unsigned long long d;
    asm("fma.rn.f32x2 %0, %1, %2, %3;" : "=l"(d) : "l"(a), "l"(b), "l"(c));
    return d;
}
__device__ __forceinline__ unsigned long long dup2(float x)
{
    unsigned long long r;
    asm("mov.b64 %0, {%1, %1};" : "=l"(r) : "f"(x));
    return r;
}
__device__ __forceinline__ float2 upk2(unsigned long long v)
{
    float2 f;
    asm("mov.b64 {%0, %1}, %2;" : "=f"(f.x), "=f"(f.y) : "l"(v));
    return f;
}

// ---------------------------------------------------------------------------
// Conv1d K=4, stride 2, pad 2, + ReLU.  FFMA2 inner loop.
// ---------------------------------------------------------------------------
__global__ __launch_bounds__(128) void conv_relu(
    const float* __restrict__ in, const float* __restrict__ w,
    const float* __restrict__ bias, float* __restrict__ out,
    int Cin, int Lin, int Lout, int mode)
{
    __shared__ float sIn[8][260];
    __shared__ float sW[16][8][4];
    int tid = threadIdx.x;
    int b = blockIdx.z, coBase = blockIdx.y * 16, tBase = blockIdx.x * 128;
    int base = 2 * tBase - 2;
    int tg = tid & 15, co_l = tid >> 4;
    unsigned long long acc0p[8], acc1p[8];
#pragma unroll
    for (int i = 0; i < 8; i++) { acc0p[i] = 0ull; acc1p[i] = 0ull; }

    for (int c0 = 0; c0 < Cin; c0 += 8) {
        for (int x = tid; x < 8 * 258; x += 128) {
            int ci = x / 258, li = x - ci * 258, p = base + li, cig = c0 + ci;
            float v = 0.f;
            if (cig < Cin && p >= 0 && p < Lin)
                v = in[(size_t)b * Cin * Lin + (size_t)cig * Lin + p];
            sIn[ci][li] = v;
        }
        for (int x = tid; x < 512; x += 128) {
            int co = x >> 5, ci = (x >> 2) & 7, kk = x & 3, cig = c0 + ci;
            sW[co][ci][kk] = (cig < Cin) ? w[((size_t)(coBase + co) * Cin + cig) * 4 + kk] : 0.f;
        }
        __syncthreads();
#pragma unroll
        for (int ci = 0; ci < 8; ci++) {
            ulonglong2 wq0 = *(const ulonglong2*)&sW[co_l][ci][0];
            ulonglong2 wq1 = *(const ulonglong2*)&sW[co_l + 8][ci][0];
#pragma unroll
            for (int jj = 0; jj < 8; jj++) {
                int li = 2 * tg + 32 * jj;
                unsigned long long pa = *(const unsigned long long*)&sIn[ci][li];
                unsigned long long pb = *(const unsigned long long*)&sIn[ci][li + 2];
                acc0p[jj] = ffma2(wq0.x, pa, acc0p[jj]);
                acc0p[jj] = ffma2(wq0.y, pb, acc0p[jj]);
                acc1p[jj] = ffma2(wq1.x, pa, acc1p[jj]);
                acc1p[jj] = ffma2(wq1.y, pb, acc1p[jj]);
            }
        }
        __syncthreads();
    }
    int co0 = coBase + co_l, co1 = co0 + 8;
    float b0 = bias[co0], b1 = bias[co1];
#pragma unroll
    for (int jj = 0; jj < 8; jj++) {
        int t = tBase + tg + 16 * jj;
        if (t < Lout) {
            float2 f0 = upk2(acc0p[jj]);
            float2 f1 = upk2(acc1p[jj]);
            float v0 = fmaxf(f0.x + f0.y + b0, 0.f);
            float v1 = fmaxf(f1.x + f1.y + b1, 0.f);
            if (mode == 0) {
                out[(size_t)b * 512 * Lout + (size_t)co0 * Lout + t] = v0;
                out[(size_t)b * 512 * Lout + (size_t)co1 * Lout + t] = v1;
            } else {
                out[(size_t)t * 4608 + b * 576 + co0] = v0;
                out[(size_t)t * 4608 + b * 576 + co1] = v1;
            }
        }
    }
}

__global__ void embfill(const float* __restrict__ emb, const int* __restrict__ subj,
                        float* __restrict__ xin)
{
    int idx = blockIdx.x * blockDim.x + threadIdx.x;
    if (idx >= TL * 8 * 64) return;
    int e = idx & 63, b = (idx >> 6) & 7, t = idx >> 9;
    xin[(size_t)t * 4608 + b * 576 + 512 + e] = emb[(size_t)subj[b] * 64 + e];
}

// ---------------------------------------------------------------------------
// GEMM 128x128 tile, 8x8 micro, FFMA2 packed over output columns (j pairs).
// mode 0: C[n*M+m]; mode 1: d_out[(b*128+m)*513+t], n=t*8+b (M=128 only).
// ---------------------------------------------------------------------------
__global__ __launch_bounds__(256) void gemm_nt(
    const float* __restrict__ Wm, const float* __restrict__ Bm, float* __restrict__ C,
    const float* __restrict__ bias1, const float* __restrict__ bias2,
    int M, int N, int K, int mode)
{
    __shared__ float sA[16 * 132];
    __shared__ float sB[16 * 132];
    int tid = threadIdx.x;
    int mBase = blockIdx.y * 128, nBase = blockIdx.x * 128;
    int r = tid & 127, kq = (tid >> 7) * 8;
    int mi = (tid & 15) * 4, ni = ((tid >> 4) & 15) * 4;

    unsigned long long accp[8][4];
#pragma unroll
    for (int i = 0; i < 8; i++)
#pragma unroll
        for (int jp = 0; jp < 4; jp++) accp[i][jp] = 0ull;

    float4 a0, a1, b0v, b1v;
    {
        const float* ap = &Wm[(size_t)(mBase + r) * K + kq];
        a0 = *(const float4*)ap; a1 = *(const float4*)(ap + 4);
        int n = nBase + r;
        if (n < N) {
            const float* bp = &Bm[(size_t)n * K + kq];
            b0v = *(const float4*)bp; b1v = *(const float4*)(bp + 4);
        } else { b0v = make_float4(0,0,0,0); b1v = b0v; }
    }

    for (int k0 = 0; k0 < K; k0 += 16) {
        __syncthreads();
        sA[(kq+0)*132+r]=a0.x; sA[(kq+1)*132+r]=a0.y; sA[(kq+2)*132+r]=a0.z; sA[(kq+3)*132+r]=a0.w;
        sA[(kq+4)*132+r]=a1.x; sA[(kq+5)*132+r]=a1.y; sA[(kq+6)*132+r]=a1.z; sA[(kq+7)*132+r]=a1.w;
        sB[(kq+0)*132+r]=b0v.x; sB[(kq+1)*132+r]=b0v.y; sB[(kq+2)*132+r]=b0v.z; sB[(kq+3)*132+r]=b0v.w;
        sB[(kq+4)*132+r]=b1v.x; sB[(kq+5)*132+r]=b1v.y; sB[(kq+6)*132+r]=b1v.z; sB[(kq+7)*132+r]=b1v.w;
        __syncthreads();
        int kn = k0 + 16;
        if (kn < K) {
            const float* ap = &Wm[(size_t)(mBase + r) * K + kn + kq];
            a0 = *(const float4*)ap; a1 = *(const float4*)(ap + 4);
            int n = nBase + r;
            if (n < N) {
                const float* bp = &Bm[(size_t)n * K + kn + kq];
                b0v = *(const float4*)bp; b1v = *(const float4*)(bp + 4);
            } else { b0v = make_float4(0,0,0,0); b1v = b0v; }
        }
#pragma unroll
        for (int kk = 0; kk < 16; kk++) {
            float4 aL = *(const float4*)&sA[kk * 132 + mi];
            float4 aH = *(const float4*)&sA[kk * 132 + mi + 64];
            ulonglong2 bLp = *(const ulonglong2*)&sB[kk * 132 + ni];
            ulonglong2 bHp = *(const ulonglong2*)&sB[kk * 132 + ni + 64];
            unsigned long long ad[8];
            ad[0]=dup2(aL.x); ad[1]=dup2(aL.y); ad[2]=dup2(aL.z); ad[3]=dup2(aL.w);
            ad[4]=dup2(aH.x); ad[5]=dup2(aH.y); ad[6]=dup2(aH.z); ad[7]=dup2(aH.w);
            unsigned long long bp[4] = {bLp.x, bLp.y, bHp.x, bHp.y};
#pragma unroll
            for (int i = 0; i < 8; i++)
#pragma unroll
                for (int jp = 0; jp < 4; jp++)
                    accp[i][jp] = ffma2(ad[i], bp[jp], accp[i][jp]);
        }
    }

    float acc[8][8];
#pragma unroll
    for (int i = 0; i < 8; i++)
#pragma unroll
        for (int jp = 0; jp < 4; jp++) {
            float2 f = upk2(accp[i][jp]);
            acc[i][2*jp] = f.x; acc[i][2*jp+1] = f.y;
        }

    float bb[8];
#pragma unroll
    for (int i = 0; i < 8; i++) {
        int m = mBase + ((i < 4) ? (mi + i) : (64 + mi + i - 4));
        float v = bias1 ? bias1[m] : 0.f;
        if (bias2) v += bias2[m];
        bb[i] = v;
    }
    if (mode == 0) {
#pragma unroll
        for (int j = 0; j < 8; j++) {
            int n = nBase + ((j < 4) ? (ni + j) : (64 + ni + j - 4));
            if (n < N) {
                float4 lo = make_float4(acc[0][j]+bb[0], acc[1][j]+bb[1], acc[2][j]+bb[2], acc[3][j]+bb[3]);
                float4 hi = make_float4(acc[4][j]+bb[4], acc[5][j]+bb[5], acc[6][j]+bb[6], acc[7][j]+bb[7]);
                *(float4*)&C[(size_t)n * M + mBase + mi] = lo;
                *(float4*)&C[(size_t)n * M + mBase + mi + 64] = hi;
            }
        }
    } else {
#pragma unroll
        for (int j = 0; j < 8; j++) {
            int n = nBase + ((j < 4) ? (ni + j) : (64 + ni + j - 4));
            if (n < N) {
                int bI = n & 7, t = n >> 3;
#pragma unroll
                for (int i = 0; i < 8; i++) {
                    int m = mBase + ((i < 4) ? (mi + i) : (64 + mi + i - 4));
                    C[(size_t)(bI * 128 + m) * 513 + t] = acc[i][j] + bb[i];
                }
            }
        }
    }
}

// ---------------------------------------------------------------------------
// Fused 2-layer wavefront LSTM.  128 CTAs x 256 thr (8 warps).
// Warps 0-3: layer0 unit u=blk*4+w; warps 4-7: layer1 unit u=blk*4+w-4.
// Step s: layer0 does t=s, layer1 does t=s-1.  514 grid barriers (R7 scheme:
// tid0-only volatile spin on last-arriver flag).
// ---------------------------------------------------------------------------
__global__ __launch_bounds__(256) void lstm2_kernel(
    const float* __restrict__ Whh0, const float* __restrict__ Gpre0,
    const float* __restrict__ Wih1, const float* __restrict__ Whh1,
    const float* __restrict__ bih1, const float* __restrict__ bhh1,
    float* __restrict__ h0seq, float* __restrict__ h1seq)
{
    __shared__ float bufA[4096];
    __shared__ float bufB[4096];
    int tid = threadIdx.x;
    int w = tid >> 5, l = tid & 31;
    int layer = w >> 2;
    int u = blockIdx.x * 4 + (w & 3);
    int gg = l >> 3, bb = l & 7;

    const float* Wrec = (layer == 0) ? Whh0 : Whh1;
    ulonglong2 wrp[4][4];
#pragma unroll
    for (int g = 0; g < 4; g++)
#pragma unroll
        for (int cc = 0; cc < 4; cc++)
            wrp[g][cc] = *(const ulonglong2*)&Wrec[(size_t)(g * 512 + u) * 512 + cc * 128 + (l << 2)];
    ulonglong2 wip[4][4];
    if (layer == 1) {
#pragma unroll
        for (int g = 0; g < 4; g++)
#pragma unroll
            for (int cc = 0; cc < 4; cc++)
                wip[g][cc] = *(const ulonglong2*)&Wih1[(size_t)(g * 512 + u) * 512 + cc * 128 + (l << 2)];
    } else {
#pragma unroll
        for (int g = 0; g < 4; g++)
#pragma unroll
            for (int cc = 0; cc < 4; cc++)
                wip[g][cc] = make_ulonglong2(0ull, 0ull);
    }
    float bias1v = (layer == 1) ? (bih1[gg * 512 + u] + bhh1[gg * 512 + u]) : 0.f;

    float c = 0.f;

    for (int s = 0; s <= TL; s++) {
        // fill bufA = h0[s-1], bufB = h1[s-2]
        if (s == 0) {
            for (int i = tid; i < 1024; i += 256) ((float4*)bufA)[i] = make_float4(0,0,0,0);
        } else {
            const float4* src = (const float4*)(h0seq + (size_t)(s - 1) * 4096);
            for (int i = tid; i < 1024; i += 256) ((float4*)bufA)[i] = __ldcg(&src[i]);
        }
        if (s <= 1) {
            for (int i = tid; i < 1024; i += 256) ((float4*)bufB)[i] = make_float4(0,0,0,0);
        } else {
            const float4* src = (const float4*)(h1seq + (size_t)(s - 2) * 4096);
            for (int i = tid; i < 1024; i += 256) ((float4*)bufB)[i] = __ldcg(&src[i]);
        }
        __syncthreads();

        int t = (layer == 0) ? s : (s - 1);
        bool active = (t >= 0) && (t < TL);
        if (active) {
            float gpre;
            if (layer == 0)
                gpre = Gpre0[(size_t)(t * 8 + bb) * 2048 + gg * 512 + u];
            else
                gpre = bias1v;

            unsigned long long accp[4][8];
#pragma unroll
            for (int g = 0; g < 4; g++)
#pragma unroll
                for (int q = 0; q < 8; q++) accp[g][q] = 0ull;

            const float* hrec = (layer == 0) ? bufA : bufB;
#pragma unroll
            for (int q = 0; q < 8; q++) {
                const float* hb = hrec + q * 512 + (l << 2);
#pragma unroll
                for (int cc = 0; cc < 4; cc++) {
                    ulonglong2 hp = *(const ulonglong2*)(hb + cc * 128);
#pragma unroll
                    for (int g = 0; g < 4; g++) {
                        accp[g][q] = ffma2(wrp[g][cc].x, hp.x, accp[g][q]);
                        accp[g][q] = ffma2(wrp[g][cc].y, hp.y, accp[g][q]);
                    }
                }
            }
            if (layer == 1) {
#pragma unroll
                for (int q = 0; q < 8; q++) {
                    const float* hb = bufA + q * 512 + (l << 2);
#pragma unroll
                    for (int cc = 0; cc < 4; cc++) {
                        ulonglong2 hp = *(const ulonglong2*)(hb + cc * 128);
#pragma unroll
                        for (int g = 0; g < 4; g++) {
                            accp[g][q] = ffma2(wip[g][cc].x, hp.x, accp[g][q]);
                            accp[g][q] = ffma2(wip[g][cc].y, hp.y, accp[g][q]);
                        }
                    }
                }
            }

            float v[32];
#pragma unroll
            for (int g = 0; g < 4; g++)
#pragma unroll
                for (int q = 0; q < 8; q++) {
                    float2 f = upk2(accp[g][q]);
                    v[g * 8 + q] = f.x + f.y;
                }
            int cnt = 32;
#pragma unroll
            for (int sft = 16; sft >= 1; sft >>= 1) {
                cnt >>= 1;
                bool up = (l & sft) != 0;
#pragma unroll
                for (int i = 0; i < cnt; i++) {
                    float give = up ? v[i] : v[i + cnt];
                    float keep = up ? v[i + cnt] : v[i];
                    v[i] = keep + __shfl_xor_sync(0xffffffffu, give, sft);
                }
            }
            float val = v[0] + gpre;
            float iv = __shfl_sync(0xffffffffu, val, bb);
            float fv = __shfl_sync(0xffffffffu, val, 8 + bb);
            float gv = __shfl_sync(0xffffffffu, val, 16 + bb);
            float ov = __shfl_sync(0xffffffffu, val, 24 + bb);
            if (l < 8) {
                float si = 1.f / (1.f + __expf(-iv));
                float sf = 1.f / (1.f + __expf(-fv));
                float so = 1.f / (1.f + __expf(-ov));
                c = sf * c + si * tanhf(gv);
                float h = so * tanhf(c);
                float* dst = (layer == 0) ? h0seq : h1seq;
                dst[(size_t)(t * 8 + l) * 512 + u] = h;
            }
        }
        __syncthreads();
        if (tid == 0) {
            __threadfence();
            unsigned target = (unsigned)(s + 1);
            unsigned old = atomicAdd(&g_bar, 1u);
            if (old == 128u * target - 1u) {
                atomicExch(&g_flag, target);
            } else {
                while (*((volatile unsigned*)&g_flag) < target) {}
            }
            __threadfence();
        }
        __syncthreads();
    }
}

// ---------------------------------------------------------------------------
// Banded rel-pos attention.
// ---------------------------------------------------------------------------
__global__ __launch_bounds__(128) void attn_kernel(
    const float* __restrict__ q, const float* __restrict__ k,
    const float* __restrict__ cn, const float* __restrict__ rel,
    float* __restrict__ outp)
{
    extern __shared__ float sm[];
    float* sq = sm;
    float* sk = sq + 16 * 64;
    float* sc = sk + 116 * 64;
    float* se = sc + 116 * 64;
    float* sw = se + 101 * 64;
    int t0 = blockIdx.x * 16, hh = blockIdx.y, b = blockIdx.z;
    int tid = threadIdx.x;
    int s0 = t0 - 50;

    for (int i = tid; i < 16 * 64; i += 128) {
        int r = i >> 6, cc = i & 63; int t = t0 + r;
        sq[i] = (t < TL) ? q[(size_t)(t * 8 + b) * 512 + hh * 64 + cc] : 0.f;
    }
    for (int i = tid; i < 116 * 64; i += 128) {
        int r = i >> 6, cc = i & 63; int s = s0 + r;
        float kv = 0.f, cv = 0.f;
        if (s >= 0 && s < TL) {
            size_t base = (size_t)(s * 8 + b) * 512 + hh * 64 + cc;
            kv = k[base]; cv = cn[base];
        }
        sk[i] = kv; sc[i] = cv;
    }
    for (int i = tid; i < 101 * 64; i += 128) se[i] = rel[i];
    __syncthreads();

    int row = tid >> 3, l8 = tid & 7;
    int t = t0 + row;
    float sco[13];
    float mx = -1e30f;
#pragma unroll
    for (int j = 0; j < 13; j++) {
        int sl = l8 + 8 * j;
        int s = t - 50 + sl;
        float v = -1e30f;
        if (sl <= 100 && s >= 0 && s < TL && t < TL) {
            const float4* qp = (const float4*)(sq + row * 64);
            const float4* kp = (const float4*)(sk + (row + sl) * 64);
            const float4* ep = (const float4*)(se + (100 - sl) * 64);
            float a = 0.f;
#pragma unroll
            for (int c4 = 0; c4 < 16; c4++) {
                float4 qv = qp[c4], kv = kp[c4], ev = ep[c4];
                a += qv.x * (kv.x + 0.3f * ev.x) + qv.y * (kv.y + 0.3f * ev.y)
                   + qv.z * (kv.z + 0.3f * ev.z) + qv.w * (kv.w + 0.3f * ev.w);
            }
            v = a;
        }
        sco[j] = v;
        mx = fmaxf(mx, v);
    }
    mx = fmaxf(mx, __shfl_xor_sync(0xffffffffu, mx, 1));
    mx = fmaxf(mx, __shfl_xor_sync(0xffffffffu, mx, 2));
    mx = fmaxf(mx, __shfl_xor_sync(0xffffffffu, mx, 4));
    float sum = 0.f;
#pragma unroll
    for (int j = 0; j < 13; j++) {
        float e = (sco[j] > -1e29f) ? __expf(sco[j] - mx) : 0.f;
        sco[j] = e; sum += e;
    }
    sum += __shfl_xor_sync(0xffffffffu, sum, 1);
    sum += __shfl_xor_sync(0xffffffffu, sum, 2);
    sum += __shfl_xor_sync(0xffffffffu, sum, 4);
    float inv = 1.f / sum;
#pragma unroll
    for (int j = 0; j < 13; j++) sw[row * 104 + l8 + 8 * j] = sco[j] * inv;
    __syncwarp();

    float4 a0 = make_float4(0.f, 0.f, 0.f, 0.f), a1 = a0;
    for (int sl = 0; sl <= 100; sl++) {
        float wv = sw[row * 104 + sl];
        const float* cp = sc + (row + sl) * 64 + l8 * 8;
        const float* ep = se + (100 - sl) * 64 + l8 * 8;
        float4 c0v = *(const float4*)cp;
        float4 c1v = *(const float4*)(cp + 4);
        float4 e0 = *(const float4*)ep;
        float4 e1 = *(const float4*)(ep + 4);
        a0.x += wv * (c0v.x + 0.3f * e0.x); a0.y += wv * (c0v.y + 0.3f * e0.y);
        a0.z += wv * (c0v.z + 0.3f * e0.z); a0.w += wv * (c0v.w + 0.3f * e0.w);
        a1.x += wv * (c1v.x + 0.3f * e1.x); a1.y += wv * (c1v.y + 0.3f * e1.y);
        a1.z += wv * (c1v.z + 0.3f * e1.z); a1.w += wv * (c1v.w + 0.3f * e1.w);
    }
    if (t < TL) {
        float* op = outp + (size_t)(t * 8 + b) * 512 + hh * 64 + l8 * 8;
        *(float4*)op = a0;
        *(float4*)(op + 4) = a1;
    }
}

__global__ void bn_part(const float* __restrict__ x, float* __restrict__ ps,
                        float* __restrict__ pq)
{
    int p = blockIdx.x, ch = threadIdx.x;
    int n0 = p * 128, n1 = n0 + 128; if (n1 > NN) n1 = NN;
    float s = 0.f, qq = 0.f;
    for (int n = n0; n < n1; n++) {
        float v = x[(size_t)n * 512 + ch];
        s += v; qq += v * v;
    }
    ps[p * 512 + ch] = s; pq[p * 512 + ch] = qq;
}

__global__ void bn_fin(const float* __restrict__ ps, const float* __restrict__ pq,
                       float* __restrict__ st)
{
    int c = threadIdx.x;
    float s = 0.f, qq = 0.f;
    for (int p = 0; p < 33; p++) { s += ps[p * 512 + c]; qq += pq[p * 512 + c]; }
    float mu = s / (float)NN;
    float var = qq / (float)NN - mu * mu;
    st[c] = mu;
    st[512 + c] = rsqrtf(var + 1e-5f);
}

__global__ void fuse_kernel(const float* __restrict__ h1, const float* __restrict__ fc,
                            const float* __restrict__ st, const float* __restrict__ g,
                            const float* __restrict__ b, const float* __restrict__ sc,
                            float* __restrict__ y)
{
    int idx = blockIdx.x * blockDim.x + threadIdx.x;
    if (idx >= NN * 512) return;
    int c = idx & 511;
    float v = (fc[idx] - st[c]) * st[512 + c] * g[c] + b[c];
    v = fmaxf(v, 0.f) * sc[c];
    y[idx] = h1[idx] + v;
}

extern "C" void kernel_launch(void* const* d_in, const int* in_sizes, int n_in,
                              void* d_out, int out_size)
{
    const float* meg  = (const float*)d_in[0];
    const float* c1w  = (const float*)d_in[1];
    const float* c1b  = (const float*)d_in[2];
    const float* c2w  = (const float*)d_in[3];
    const float* c2b  = (const float*)d_in[4];
    const float* semb = (const float*)d_in[5];
    const float* Wih0 = (const float*)d_in[6];
    const float* Whh0 = (const float*)d_in[7];
    const float* bih0 = (const float*)d_in[8];
    const float* bhh0 = (const float*)d_in[9];
    const float* Wih1 = (const float*)d_in[10];
    const float* Whh1 = (const float*)d_in[11];
    const float* bih1 = (const float*)d_in[12];
    const float* bhh1 = (const float*)d_in[13];
    const float* qw = (const float*)d_in[14];
    const float* qb = (const float*)d_in[15];
    const float* kw = (const float*)d_in[16];
    const float* kb = (const float*)d_in[17];
    const float* cw = (const float*)d_in[18];
    const float* cb = (const float*)d_in[19];
    const float* rel = (const float*)d_in[20];
    const float* fcw = (const float*)d_in[21];
    const float* fcb = (const float*)d_in[22];
    const float* bng = (const float*)d_in[23];
    const float* bnb = (const float*)d_in[24];
    const float* ascale = (const float*)d_in[25];
    const float* ow = (const float*)d_in[26];
    const float* ob = (const float*)d_in[27];
    const int* subj = (const int*)d_in[28];
    float* out = (float*)d_out;

    float *c1p, *xinp, *G0p, *h0p, *h1p, *qp, *kp, *cnp, *atp, *fcp, *yp, *psp, *pqp, *stp;
    cudaGetSymbolAddress((void**)&c1p,  g_c1);
    cudaGetSymbolAddress((void**)&xinp, g_xin);
    cudaGetSymbolAddress((void**)&G0p,  g_G0);
    cudaGetSymbolAddress((void**)&h0p,  g_h0);
    cudaGetSymbolAddress((void**)&h1p,  g_h1);
    cudaGetSymbolAddress((void**)&qp,   g_q);
    cudaGetSymbolAddress((void**)&kp,   g_k);
    cudaGetSymbolAddress((void**)&cnp,  g_cn);
    cudaGetSymbolAddress((void**)&atp,  g_at);
    cudaGetSymbolAddress((void**)&fcp,  g_fc);
    cudaGetSymbolAddress((void**)&yp,   g_y);
    cudaGetSymbolAddress((void**)&psp,  g_ps);
    cudaGetSymbolAddress((void**)&pqp,  g_pq);
    cudaGetSymbolAddress((void**)&stp,  g_st);

    cudaFuncSetAttribute(attn_kernel, cudaFuncAttributeMaxDynamicSharedMemorySize, 96000);

    conv_relu<<<dim3(9, 32, 8), 128>>>(meg, c1w, c1b, c1p, 273, 2048, 1025, 0);
    conv_relu<<<dim3(5, 32, 8), 128>>>(c1p, c2w, c2b, xinp, 512, 1025, 513, 1);
    embfill<<<(TL * 8 * 64 + 255) / 256, 256>>>(semb, subj, xinp);

    gemm_nt<<<dim3(33, 16), 256>>>(Wih0, xinp, G0p, bih0, bhh0, 2048, NN, 576, 0);
    bar_reset<<<1, 1>>>();
    lstm2_kernel<<<128, 256>>>(Whh0, G0p, Wih1, Whh1, bih1, bhh1, h0p, h1p);

    gemm_nt<<<dim3(33, 4), 256>>>(qw, h1p, qp, qb, (const float*)0, 512, NN, 512, 0);
    gemm_nt<<<dim3(33, 4), 256>>>(kw, h1p, kp, kb, (const float*)0, 512, NN, 512, 0);
    gemm_nt<<<dim3(33, 4), 256>>>(cw, h1p, cnp, cb, (const float*)0, 512, NN, 512, 0);

    attn_kernel<<<dim3(33, 8, 8), 128, 96000>>>(qp, kp, cnp, rel, atp);

    gemm_nt<<<dim3(33, 4), 256>>>(fcw, atp, fcp, fcb, (const float*)0, 512, NN, 512, 0);
    bn_part<<<33, 512>>>(fcp, psp, pqp);
    bn_fin<<<1, 512>>>(psp, pqp, stp);
    fuse_kernel<<<(NN * 512 + 255) / 256, 256>>>(h1p, fcp, stp, bng, bnb, ascale, yp);

    gemm_nt<<<dim3(33, 1), 256>>>(ow, yp, out, ob, (const float*)0, 128, NN, 512, 1);
}